// round 17
// baseline (speedup 1.0000x reference)
#include <cuda_runtime.h>
#include <math.h>

#define N_NODES 50000
#define N_EDGES 800000
#define IN_DIM  256
#define C1      128     // HEADS * 32
#define HEADS   4
#define HID1    32
#define OUT_DIM 64

typedef unsigned long long u64;

// ---------------- scratch (device globals; no allocation allowed) ------------
__device__ __align__(16) float g_z1 [N_NODES * C1];
__device__ __align__(16) float g_es1[N_NODES * HEADS];
__device__ __align__(16) float g_ed1[N_NODES * HEADS];
__device__ __align__(16) float g_h1 [N_NODES * C1];
__device__ __align__(16) float g_z2 [N_NODES * OUT_DIM];
__device__ float g_es2[N_NODES];
__device__ float g_ed2[N_NODES];
__device__ int   g_deg[N_NODES];
__device__ int   g_pos[N_NODES];
__device__ int   g_off[N_NODES + 1];
__device__ __align__(16) int g_ssrc[N_EDGES];

__device__ __forceinline__ float leaky(float x) { return x > 0.f ? x : 0.01f * x; }
__device__ __forceinline__ float elu_f(float x) { return x > 0.f ? x : (__expf(x) - 1.f); }

// packed fp32x2 FMA (sm_100+): d = a*b + c elementwise on 2 packed floats
__device__ __forceinline__ u64 ffma2(u64 a, u64 b, u64 c) {
    u64 d;
    asm("fma.rn.f32x2 %0, %1, %2, %3;" : "=l"(d) : "l"(a), "l"(b), "l"(c));
    return d;
}
// duplicate one fp32 into both lanes of a packed f32x2
__device__ __forceinline__ u64 dup2(float x) {
    u64 d; unsigned b = __float_as_uint(x);
    asm("mov.b64 %0, {%1, %1};" : "=l"(d) : "r"(b));
    return d;
}
__device__ __forceinline__ float f2lo(u64 v) { return __uint_as_float((unsigned)v); }
__device__ __forceinline__ float f2hi(u64 v) { return __uint_as_float((unsigned)(v >> 32)); }

// ---------------- CSR build --------------------------------------------------
__global__ void k_zero() {
    int i = blockIdx.x * blockDim.x + threadIdx.x;
    if (i < N_NODES) { g_deg[i] = 0; g_pos[i] = 0; }
}

__global__ void k_hist(const int* __restrict__ dst) {
    int e = blockIdx.x * blockDim.x + threadIdx.x;
    if (e < N_EDGES) atomicAdd(&g_deg[dst[e]], 1);
}

__global__ void k_scan() {
    __shared__ int sm[1024];
    int tid = threadIdx.x;
    const int CH = (N_NODES + 1023) / 1024;   // 49
    int base = tid * CH;
    int s = 0;
    for (int i = 0; i < CH; i++) {
        int idx = base + i;
        if (idx < N_NODES) s += g_deg[idx];
    }
    sm[tid] = s;
    __syncthreads();
    for (int d = 1; d < 1024; d <<= 1) {
        int v = (tid >= d) ? sm[tid - d] : 0;
        __syncthreads();
        sm[tid] += v;
        __syncthreads();
    }
    int run = sm[tid] - s;   // exclusive prefix
    for (int i = 0; i < CH; i++) {
        int idx = base + i;
        if (idx < N_NODES) { g_off[idx] = run; run += g_deg[idx]; }
    }
    if (tid == 1023) g_off[N_NODES] = sm[1023];
}

__global__ void k_scatter(const int* __restrict__ src, const int* __restrict__ dst) {
    int e = blockIdx.x * blockDim.x + threadIdx.x;
    if (e < N_EDGES) {
        int d = dst[e];
        int p = g_off[d] + atomicAdd(&g_pos[d], 1);
        g_ssrc[p] = src[e];
    }
}

// ---------------- layer-1 GEMM + attention coeffs (fused) --------------------
__global__ void __launch_bounds__(256, 1) k_gemm1(const float* __restrict__ x,
                                                  const float* __restrict__ W1,
                                                  const float* __restrict__ a1) {
    extern __shared__ float sm[];
    float* sW = sm;                  // 256*128 floats
    float* sx = sm + 256 * 128;      // 64*256 floats
    int tid = threadIdx.x;           // 256 threads

    // W1 [h][k][d] -> sW[k][h*32+d]
    for (int i = tid; i < HEADS * IN_DIM * HID1; i += 256) {
        int hh = i >> 13, k = (i >> 5) & 255, d = i & 31;
        sW[k * 128 + hh * 32 + d] = W1[i];
    }

    int lane = tid & 31;
    int c0 = lane * 4;                // lane-varying col group (conflict-free)
    int nr = (tid >> 5) * 8;          // warp-uniform node group (broadcast)
    int hl = lane >> 3;               // head owned by this lane
    int d0 = c0 & 31;                 // offset within head
    const float4 as4 = *(const float4*)&a1[hl * 64 + d0];
    const float4 ad4 = *(const float4*)&a1[hl * 64 + 32 + d0];
    int ntiles = (N_NODES + 63) >> 6;

    for (int tile = blockIdx.x; tile < ntiles; tile += gridDim.x) {
        int n0 = tile << 6;
        __syncthreads();
        for (int i = tid; i < 64 * 64; i += 256) {
            int n = n0 + (i >> 6);
            float4 v = make_float4(0.f, 0.f, 0.f, 0.f);
            if (n < N_NODES) v = ((const float4*)x)[n * 64 + (i & 63)];
            ((float4*)sx)[i] = v;
        }
        __syncthreads();

        u64 acc[8][2];
        #pragma unroll
        for (int j = 0; j < 8; j++) { acc[j][0] = 0ull; acc[j][1] = 0ull; }

        const float* xs = sx + nr * 256;
        #pragma unroll 2
        for (int k = 0; k < 256; k += 4) {
            ulonglong2 wp[4];
            #pragma unroll
            for (int kk = 0; kk < 4; kk++)
                wp[kk] = *(const ulonglong2*)&sW[(k + kk) * 128 + c0];
            #pragma unroll
            for (int j = 0; j < 8; j++) {
                float4 xv = *(const float4*)&xs[j * 256 + k];
                u64 x0 = dup2(xv.x), x1 = dup2(xv.y);
                u64 x2 = dup2(xv.z), x3 = dup2(xv.w);
                acc[j][0] = ffma2(x0, wp[0].x, acc[j][0]);
                acc[j][1] = ffma2(x0, wp[0].y, acc[j][1]);
                acc[j][0] = ffma2(x1, wp[1].x, acc[j][0]);
                acc[j][1] = ffma2(x1, wp[1].y, acc[j][1]);
                acc[j][0] = ffma2(x2, wp[2].x, acc[j][0]);
                acc[j][1] = ffma2(x2, wp[2].y, acc[j][1]);
                acc[j][0] = ffma2(x3, wp[3].x, acc[j][0]);
                acc[j][1] = ffma2(x3, wp[3].y, acc[j][1]);
            }
        }

        #pragma unroll
        for (int j = 0; j < 8; j++) {
            int n = n0 + nr + j;          // warp-uniform
            float4 o;
            o.x = f2lo(acc[j][0]); o.y = f2hi(acc[j][0]);
            o.z = f2lo(acc[j][1]); o.w = f2hi(acc[j][1]);
            float es = o.x * as4.x + o.y * as4.y + o.z * as4.z + o.w * as4.w;
            float ed = o.x * ad4.x + o.y * ad4.y + o.z * ad4.z + o.w * ad4.w;
            #pragma unroll
            for (int m = 4; m; m >>= 1) {
                es += __shfl_xor_sync(0xffffffffu, es, m);
                ed += __shfl_xor_sync(0xffffffffu, ed, m);
            }
            if (n < N_NODES) {
                ulonglong2 ov; ov.x = acc[j][0]; ov.y = acc[j][1];
                *(ulonglong2*)&g_z1[n * 128 + c0] = ov;
                if ((lane & 7) == 0) {
                    g_es1[n * 4 + hl] = es;
                    g_ed1[n * 4 + hl] = ed;
                }
            }
        }
    }
}

// ---------------- layer-1 aggregation: warp per node, convergent, batched ----
// All 32 lanes convergent; 4 edges per chunk with every load front-batched.
// Tail edges handled by predicating ex to 0 (index 0 as safe dummy).
__global__ void __launch_bounds__(256) k_agg1() {
    int gw   = (blockIdx.x * blockDim.x + threadIdx.x) >> 5;
    int lane = threadIdx.x & 31;
    if (gw >= N_NODES) return;
    int hl = lane >> 3;             // head owned by this lane
    int cc = lane * 4;              // 4 channels per lane

    int off = g_off[gw];
    int deg = g_off[gw + 1] - off;
    int end = off + deg;
    float edv = g_ed1[gw * 4 + hl];

    float4 acc = make_float4(0.f, 0.f, 0.f, 0.f);
    float dsum = 0.f;

    for (int i = off; i < end; i += 4) {
        int rem = end - i;
        // batch index loads (warp-uniform)
        int s0 = g_ssrc[i];
        int s1 = (rem > 1) ? g_ssrc[i + 1] : 0;
        int s2 = (rem > 2) ? g_ssrc[i + 2] : 0;
        int s3 = (rem > 3) ? g_ssrc[i + 3] : 0;
        // batch es gathers (4B each, 1 sector per instruction)
        float e0 = g_es1[s0 * 4 + hl];
        float e1 = g_es1[s1 * 4 + hl];
        float e2 = g_es1[s2 * 4 + hl];
        float e3 = g_es1[s3 * 4 + hl];
        // batch z-row gathers (LDG.128 each)
        float4 z0 = *(const float4*)&g_z1[s0 * 128 + cc];
        float4 z1 = *(const float4*)&g_z1[s1 * 128 + cc];
        float4 z2 = *(const float4*)&g_z1[s2 * 128 + cc];
        float4 z3 = *(const float4*)&g_z1[s3 * 128 + cc];
        // softmax weights (no max-shift; |e| << 88 so exp is safe)
        float x0 = __expf(leaky(e0 + edv));
        float x1 = (rem > 1) ? __expf(leaky(e1 + edv)) : 0.f;
        float x2 = (rem > 2) ? __expf(leaky(e2 + edv)) : 0.f;
        float x3 = (rem > 3) ? __expf(leaky(e3 + edv)) : 0.f;
        dsum += x0 + x1 + x2 + x3;
        acc.x += x0 * z0.x + x1 * z1.x + x2 * z2.x + x3 * z3.x;
        acc.y += x0 * z0.y + x1 * z1.y + x2 * z2.y + x3 * z3.y;
        acc.z += x0 * z0.z + x1 * z1.z + x2 * z2.z + x3 * z3.z;
        acc.w += x0 * z0.w + x1 * z1.w + x2 * z2.w + x3 * z3.w;
    }

    float inv = (deg > 0) ? (1.0f / dsum) : 0.f;
    float4 o;
    o.x = elu_f(acc.x * inv);
    o.y = elu_f(acc.y * inv);
    o.z = elu_f(acc.z * inv);
    o.w = elu_f(acc.w * inv);
    *(float4*)&g_h1[gw * 128 + cc] = o;
}

// ---------------- layer-2 GEMM + attention coeffs (fused) --------------------
__global__ void __launch_bounds__(256) k_gemm2(const float* __restrict__ W2,
                                               const float* __restrict__ a2) {
    extern __shared__ float sm[];
    float* sW = sm;                 // 128*64 floats
    float* sx = sm + 128 * 64;      // 64*128 floats
    int tid = threadIdx.x;          // 256 threads

    for (int i = tid; i < 128 * 64; i += 256) sW[i] = W2[i];

    int lane = tid & 31;
    int c0 = (tid & 15) * 4;        // 16 col-groups of 4
    int nr = (tid >> 4) * 4;        // 16 node-groups of 4 (uniform per half-warp)
    const float4 as4 = *(const float4*)&a2[c0];
    const float4 ad4 = *(const float4*)&a2[64 + c0];
    int ntiles = (N_NODES + 63) >> 6;

    for (int tile = blockIdx.x; tile < ntiles; tile += gridDim.x) {
        int n0 = tile << 6;
        __syncthreads();
        for (int i = tid; i < 64 * 32; i += 256) {
            int n = n0 + (i >> 5);
            float4 v = make_float4(0.f, 0.f, 0.f, 0.f);
            if (n < N_NODES) v = ((const float4*)g_h1)[n * 32 + (i & 31)];
            ((float4*)sx)[i] = v;
        }
        __syncthreads();

        u64 acc[4][2];
        #pragma unroll
        for (int j = 0; j < 4; j++) { acc[j][0] = 0ull; acc[j][1] = 0ull; }

        const float* xs = sx + nr * 128;
        #pragma unroll 2
        for (int k = 0; k < 128; k += 4) {
            ulonglong2 wp[4];
            #pragma unroll
            for (int kk = 0; kk < 4; kk++)
                wp[kk] = *(const ulonglong2*)&sW[(k + kk) * 64 + c0];
            #pragma unroll
            for (int j = 0; j < 4; j++) {
                float4 xv = *(const float4*)&xs[j * 128 + k];
                u64 x0 = dup2(xv.x), x1 = dup2(xv.y);
                u64 x2 = dup2(xv.z), x3 = dup2(xv.w);
                acc[j][0] = ffma2(x0, wp[0].x, acc[j][0]);
                acc[j][1] = ffma2(x0, wp[0].y, acc[j][1]);
                acc[j][0] = ffma2(x1, wp[1].x, acc[j][0]);
                acc[j][1] = ffma2(x1, wp[1].y, acc[j][1]);
                acc[j][0] = ffma2(x2, wp[2].x, acc[j][0]);
                acc[j][1] = ffma2(x2, wp[2].y, acc[j][1]);
                acc[j][0] = ffma2(x3, wp[3].x, acc[j][0]);
                acc[j][1] = ffma2(x3, wp[3].y, acc[j][1]);
            }
        }

        #pragma unroll
        for (int j = 0; j < 4; j++) {
            int n = n0 + nr + j;      // uniform per half-warp
            float4 o;
            o.x = f2lo(acc[j][0]); o.y = f2hi(acc[j][0]);
            o.z = f2lo(acc[j][1]); o.w = f2hi(acc[j][1]);
            float es = o.x * as4.x + o.y * as4.y + o.z * as4.z + o.w * as4.w;
            float ed = o.x * ad4.x + o.y * ad4.y + o.z * ad4.z + o.w * ad4.w;
            #pragma unroll
            for (int m = 8; m; m >>= 1) {
                es += __shfl_xor_sync(0xffffffffu, es, m);
                ed += __shfl_xor_sync(0xffffffffu, ed, m);
            }
            if (n < N_NODES) {
                ulonglong2 ov; ov.x = acc[j][0]; ov.y = acc[j][1];
                *(ulonglong2*)&g_z2[n * 64 + c0] = ov;
                if ((lane & 15) == 0) {
                    g_es2[n] = es;
                    g_ed2[n] = ed;
                }
            }
        }
    }
}

// ---------------- layer-2 aggregation: warp per node, convergent, batched ----
// Lane owns 2 channels (LDG.64); 8 edges per chunk, loads front-batched.
__global__ void __launch_bounds__(256) k_agg2(float* __restrict__ out) {
    int gw   = (blockIdx.x * blockDim.x + threadIdx.x) >> 5;
    int lane = threadIdx.x & 31;
    if (gw >= N_NODES) return;
    int cc = lane * 2;

    int off = g_off[gw];
    int deg = g_off[gw + 1] - off;
    int end = off + deg;
    float edv = g_ed2[gw];

    float2 acc = make_float2(0.f, 0.f);
    float dsum = 0.f;

    for (int i = off; i < end; i += 8) {
        int rem = end - i;
        int   ss[8]; float ev[8]; float2 zv[8]; float xv[8];
        #pragma unroll
        for (int u = 0; u < 8; u++)
            ss[u] = (u < rem) ? g_ssrc[i + u] : 0;
        #pragma unroll
        for (int u = 0; u < 8; u++)
            ev[u] = g_es2[ss[u]];
        #pragma unroll
        for (int u = 0; u < 8; u++)
            zv[u] = *(const float2*)&g_z2[ss[u] * 64 + cc];
        #pragma unroll
        for (int u = 0; u < 8; u++)
            xv[u] = (u < rem) ? __expf(leaky(ev[u] + edv)) : 0.f;
        #pragma unroll
        for (int u = 0; u < 8; u++) {
            dsum += xv[u];
            acc.x += xv[u] * zv[u].x;
            acc.y += xv[u] * zv[u].y;
        }
    }

    float inv = (deg > 0) ? (1.0f / dsum) : 0.f;
    float2 o;
    o.x = acc.x * inv;
    o.y = acc.y * inv;
    *(float2*)&out[gw * 64 + cc] = o;
}

// ---------------- launch -----------------------------------------------------
extern "C" void kernel_launch(void* const* d_in, const int* in_sizes, int n_in,
                              void* d_out, int out_size) {
    const float* h   = (const float*)d_in[0];
    const int*   src = (const int*)  d_in[1];
    const int*   dst = (const int*)  d_in[2];
    const float* W1  = (const float*)d_in[3];
    const float* a1  = (const float*)d_in[4];
    const float* W2  = (const float*)d_in[5];
    const float* a2  = (const float*)d_in[6];
    float* out = (float*)d_out;

    const int SMEM1 = (256 * 128 + 64 * 256) * 4;   // 196608
    const int SMEM2 = (128 * 64 + 64 * 128) * 4;    //  65536
    cudaFuncSetAttribute(k_gemm1, cudaFuncAttributeMaxDynamicSharedMemorySize, SMEM1);
    cudaFuncSetAttribute(k_gemm2, cudaFuncAttributeMaxDynamicSharedMemorySize, SMEM2);

    // Fork: CSR build (depends only on src/dst) runs concurrently with gemm1
    // (depends only on h/W1/a1). Capture-safe event fork/join.
    cudaStream_t side;
    cudaEvent_t evF, evJ;
    cudaStreamCreateWithFlags(&side, cudaStreamNonBlocking);
    cudaEventCreateWithFlags(&evF, cudaEventDisableTiming);
    cudaEventCreateWithFlags(&evJ, cudaEventDisableTiming);

    cudaEventRecord(evF, 0);
    cudaStreamWaitEvent(side, evF, 0);

    // side stream: CSR build (dst shared by both layers)
    k_zero   <<<(N_NODES + 255) / 256, 256, 0, side>>>();
    k_hist   <<<(N_EDGES + 255) / 256, 256, 0, side>>>(dst);
    k_scan   <<<1, 1024, 0, side>>>();
    k_scatter<<<(N_EDGES + 255) / 256, 256, 0, side>>>(src, dst);
    cudaEventRecord(evJ, side);

    // main stream: layer-1 GEMM + attention coeffs (independent of CSR)
    k_gemm1<<<148, 256, SMEM1>>>(h, W1, a1);

    // join: agg1 needs both CSR and gemm1 outputs
    cudaStreamWaitEvent(0, evJ, 0);
    k_agg1 <<<(N_NODES * 32 + 255) / 256, 256>>>();     // warp per node

    // layer 2
    k_gemm2<<<296, 256, SMEM2>>>(W2, a2);
    k_agg2 <<<(N_NODES * 32 + 255) / 256, 256>>>(out);  // warp per node
}